// round 1
// baseline (speedup 1.0000x reference)
#include <cuda_runtime.h>

// Problem constants
#define NB 8     // batch
#define TT 8     // time (we use slice t = TT/2 = 4)
#define V  512   // nodes
#define F  64    // features
#define JT 32    // j-columns per block
#define TPB 256  // threads per block: 32 j x 8 i-groups
#define SU_STRIDE 68  // padded smem row stride (floats): 16B-aligned, reduces bank conflicts

// ---- packed f32x2 helpers (Blackwell sm_100+) ----
__device__ __forceinline__ unsigned long long f2add(unsigned long long a, unsigned long long b) {
    unsigned long long r;
    asm("add.rn.f32x2 %0, %1, %2;" : "=l"(r) : "l"(a), "l"(b));
    return r;
}
__device__ __forceinline__ unsigned long long f2fma(unsigned long long a, unsigned long long b,
                                                    unsigned long long c) {
    unsigned long long r;
    asm("fma.rn.f32x2 %0, %1, %2, %3;" : "=l"(r) : "l"(a), "l"(b), "l"(c));
    return r;
}
__device__ __forceinline__ unsigned long long pk2(float lo, float hi) {
    unsigned long long r;
    asm("mov.b64 %0, {%1, %2};" : "=l"(r) : "f"(lo), "f"(hi));
    return r;
}
__device__ __forceinline__ float psum(unsigned long long v) {
    float lo, hi;
    asm("mov.b64 {%0, %1}, %2;" : "=f"(lo), "=f"(hi) : "l"(v));
    return lo + hi;
}

// One CTA per (n, j-tile of 32 columns). CTA holds all 512 i-rows, so the
// axis=1 (over i) softmax normalization is fully intra-block.
__global__ __launch_bounds__(TPB)
void graph_learn_kernel(const float* __restrict__ x,
                        const float* __restrict__ a,
                        float* __restrict__ out) {
    extern __shared__ float smem[];
    float* su      = smem;                     // V * SU_STRIDE   (xm slice, padded rows)
    float* stmp    = su + V * SU_STRIDE;       // V * JT          (exp(relu(score)))
    float* partial = stmp + V * JT;            // 8 * 32          (per-igroup column sums)
    float* colinv  = partial + 8 * 32;         // 32              (1/colsum)
    float* sa      = colinv + 32;              // F               (a vector)

    const int n   = blockIdx.y;
    const int j0  = blockIdx.x * JT;
    const int tid = threadIdx.x;
    const int j   = tid & 31;    // local column
    const int ig  = tid >> 5;    // i-group (0..7), 64 rows each

    // ---- stage xm[n] = x[n, 4, :, :] into smem (contiguous 128KB chunk) ----
    const float4* xg = (const float4*)(x + ((size_t)n * TT + TT / 2) * V * F);
    for (int idx = tid; idx < V * F / 4; idx += TPB) {
        int v = idx >> 4, k = idx & 15;
        *(float4*)(su + v * SU_STRIDE + k * 4) = xg[idx];
    }
    if (tid < F) sa[tid] = a[tid];
    __syncthreads();

    // ---- per-thread register state: -xj (packed pairs) and a (packed pairs) ----
    unsigned long long xjn[F / 2];
    unsigned long long a2[F / 2];
    {
        const float* xjrow = su + (j0 + j) * SU_STRIDE;
#pragma unroll
        for (int k = 0; k < F / 2; k++) {
            float2 w = *(const float2*)(xjrow + 2 * k);
            xjn[k] = pk2(-w.x, -w.y);
            a2[k]  = pk2(sa[2 * k], sa[2 * k + 1]);
        }
    }

    const unsigned long long ABS2 = 0x7FFFFFFF7FFFFFFFull;
    const int ibase = ig * (V / 8);
    float lsum = 0.0f;

    for (int ii = 0; ii < V / 8; ii++) {
        const int i = ibase + ii;
        const ulonglong2* xi = (const ulonglong2*)(su + i * SU_STRIDE);
        unsigned long long acc0 = 0ull, acc1 = 0ull;
#pragma unroll
        for (int k4 = 0; k4 < F / 4; k4++) {
            ulonglong2 q = xi[k4];  // LDS.128, broadcast across the 32 j-lanes
            unsigned long long d0 = f2add(q.x, xjn[2 * k4]) & ABS2;      // |xi - xj| (2 lanes)
            acc0 = f2fma(d0, a2[2 * k4], acc0);
            unsigned long long d1 = f2add(q.y, xjn[2 * k4 + 1]) & ABS2;
            acc1 = f2fma(d1, a2[2 * k4 + 1], acc1);
        }
        float s = psum(acc0) + psum(acc1);
        float t = __expf(fmaxf(s, 0.0f));  // exp(relu(score))
        lsum += t;
        stmp[i * JT + j] = t;
    }

    // ---- column sums over i (axis=1) ----
    partial[ig * 32 + j] = lsum;
    __syncthreads();
    if (tid < 32) {
        float s = 0.0f;
#pragma unroll
        for (int g = 0; g < 8; g++) s += partial[g * 32 + tid];
        colinv[tid] = 1.0f / s;
    }
    __syncthreads();

    // ---- normalize + write: warp lanes = consecutive j -> 128B coalesced stores ----
    const float inv = colinv[j];
    float* ocol = out + (size_t)n * V * V + j0 + j;
    for (int ii = 0; ii < V / 8; ii++) {
        int i = ibase + ii;
        ocol[(size_t)i * V] = stmp[i * JT + j] * inv;
    }
}

extern "C" void kernel_launch(void* const* d_in, const int* in_sizes, int n_in,
                              void* d_out, int out_size) {
    const float* x = (const float*)d_in[0];
    const float* a = (const float*)d_in[1];
    // Defensive: tolerate swapped metadata order
    if (n_in >= 2 && in_sizes[0] == F && in_sizes[1] == NB * TT * V * F) {
        const float* t = x; x = a; a = t;
    }
    float* out = (float*)d_out;

    size_t smem_bytes = (size_t)(V * SU_STRIDE + V * JT + 8 * 32 + 32 + F) * sizeof(float);
    cudaFuncSetAttribute(graph_learn_kernel,
                         cudaFuncAttributeMaxDynamicSharedMemorySize, (int)smem_bytes);

    dim3 grid(V / JT, NB);
    graph_learn_kernel<<<grid, TPB, smem_bytes>>>(x, a, out);
}